// round 13
// baseline (speedup 1.0000x reference)
#include <cuda_runtime.h>
#include <cuda_bf16.h>
#include <cstdint>
#include <math.h>

#define N_NODES   100000
#define N_EDGES   1600000
#define E_TOT     (N_EDGES + N_NODES)
#define IN_DIM    256
#define HID       64
#define HEADS     3
#define OUTC      (HEADS * HID)         // 192
#define NUM_CLASSES 10
#define NUM_GRAPHS  64

#define SCAN_BLK  1024
#define N_SBLKS   ((N_NODES + SCAN_BLK - 1) / SCAN_BLK)   // 98

#define M_TILE    128
#define N_TILES_M 782                   // ceil(100000/128)
#define ROWS_PAD  (N_TILES_M * M_TILE)  // 100096

// fused prep kernel grid layout
#define PREP_A_BLOCKS (ROWS_PAD * 64 / 256)                 // 25024
#define PREP_B_BLOCKS ((2 * OUTC * 64 + 255) / 256)         // 96
#define ZERO_LEN      (N_NODES + 1 + N_SBLKS)
#define ZERO_BLOCKS   ((ZERO_LEN + 255) / 256)
#define FUSED_BLOCKS  (PREP_A_BLOCKS + PREP_B_BLOCKS + ZERO_BLOCKS)

// ---------------- scratch ----------------------------------------------------
__device__ float g_xl[N_NODES * OUTC];
__device__ float g_xr[N_NODES * OUTC];
__device__ int   g_deg[N_NODES + 1];
__device__ int   g_off[N_NODES + 1];
__device__ int   g_cur[N_NODES];
__device__ int   g_csr[E_TOT];
__device__ int   g_bsum[N_SBLKS];
__device__ int   g_flag[N_SBLKS];
// decomposed operands: packed bf16 pairs (k, k+1) as uint32 words
__device__ __align__(16) unsigned g_ahw[ROWS_PAD * (IN_DIM / 2)];       // hi(x)
__device__ __align__(16) unsigned g_alw[ROWS_PAD * (IN_DIM / 2)];       // lo(x)
__device__ __align__(16) unsigned g_bhw[2 * OUTC * (IN_DIM / 2)];       // hi(W^T)
__device__ __align__(16) unsigned g_blw[2 * OUTC * (IN_DIM / 2)];       // lo(W^T)

static __device__ __forceinline__ int clampi(int v, int lo, int hi) {
    return v < lo ? lo : (v > hi ? hi : v);
}

static __device__ __forceinline__ unsigned pack_bf16(unsigned short a, unsigned short b) {
    return (unsigned)a | ((unsigned)b << 16);
}

static __device__ __forceinline__ void split_bf16(float f, unsigned short& h, unsigned short& l) {
    __nv_bfloat16 hb = __float2bfloat16(f);
    __nv_bfloat16 lb = __float2bfloat16(f - __bfloat162float(hb));
    h = __bfloat16_as_ushort(hb);
    l = __bfloat16_as_ushort(lb);
}

// ---------------- fused prep: prep_a | prep_b | zero(deg,flags) --------------
__global__ __launch_bounds__(256) void fused_prep_kernel(
    const float* __restrict__ x,
    const float* __restrict__ Wl, const float* __restrict__ Wr)
{
    const int bid = blockIdx.x;
    const int tid = threadIdx.x;
    if (bid < PREP_A_BLOCKS) {
        int t = bid * 256 + tid;
        int k4  = t & 63;
        int row = t >> 6;
        float4 v = make_float4(0.f, 0.f, 0.f, 0.f);
        if (row < N_NODES) v = *(const float4*)(x + (size_t)row * IN_DIM + k4 * 4);
        float f[4] = {v.x, v.y, v.z, v.w};
        unsigned short h[4], l[4];
        #pragma unroll
        for (int j = 0; j < 4; j++) split_bf16(f[j], h[j], l[j]);
        int base = row * (IN_DIM / 2) + k4 * 2;
        g_ahw[base]     = pack_bf16(h[0], h[1]);
        g_ahw[base + 1] = pack_bf16(h[2], h[3]);
        g_alw[base]     = pack_bf16(l[0], l[1]);
        g_alw[base + 1] = pack_bf16(l[2], l[3]);
    } else if (bid < PREP_A_BLOCKS + PREP_B_BLOCKS) {
        int t = (bid - PREP_A_BLOCKS) * 256 + tid;
        if (t >= 2 * OUTC * 64) return;
        int k4 = t & 63;
        int n  = (t >> 6) % OUTC;
        int s  = t / (OUTC * 64);
        const float* W = s ? Wr : Wl;
        float f[4];
        #pragma unroll
        for (int j = 0; j < 4; j++) f[j] = W[(size_t)(k4 * 4 + j) * OUTC + n];
        unsigned short h[4], l[4];
        #pragma unroll
        for (int j = 0; j < 4; j++) split_bf16(f[j], h[j], l[j]);
        int base = (s * OUTC + n) * (IN_DIM / 2) + k4 * 2;
        g_bhw[base]     = pack_bf16(h[0], h[1]);
        g_bhw[base + 1] = pack_bf16(h[2], h[3]);
        g_blw[base]     = pack_bf16(l[0], l[1]);
        g_blw[base + 1] = pack_bf16(l[2], l[3]);
    } else {
        int z = (bid - PREP_A_BLOCKS - PREP_B_BLOCKS) * 256 + tid;
        if (z <= N_NODES) g_deg[z] = 0;
        int f = z - (N_NODES + 1);
        if (f >= 0 && f < N_SBLKS) { g_flag[f] = 0; g_bsum[f] = 0; }
    }
}

// ---------------- deg count (self-loop handled as +1 inside scan) ------------
__global__ void deg_count_kernel(const int* __restrict__ ei) {
    int e = blockIdx.x * blockDim.x + threadIdx.x;
    if (e < N_EDGES) {
        int d = clampi(ei[N_EDGES + e], 0, N_NODES - 1);
        atomicAdd(&g_deg[d], 1);
    }
}

// ---------------- single-kernel scan (98 blocks, all resident) ---------------
__global__ __launch_bounds__(SCAN_BLK) void scan_kernel() {
    __shared__ int s[SCAN_BLK];
    __shared__ int prev_s;
    const int tid = threadIdx.x;
    const int bid = blockIdx.x;
    const int idx = bid * SCAN_BLK + tid;

    int v = (idx < N_NODES) ? g_deg[idx] + 1 : 0;   // +1 = self loop
    int sum = v;
    #pragma unroll
    for (int off = 1; off < SCAN_BLK; off <<= 1) {
        s[tid] = sum;
        __syncthreads();
        if (tid >= off) sum += s[tid - off];
        __syncthreads();
    }
    s[tid] = sum;
    __syncthreads();
    int total = s[SCAN_BLK - 1];

    // publish own aggregate
    if (tid == 0) {
        g_bsum[bid] = total;
        __threadfence();
        atomicExch(&g_flag[bid], 1);
    }

    // lookback: thread t < bid spins for block t's aggregate
    int part = 0;
    if (tid < bid) {
        while (atomicAdd(&g_flag[tid], 0) == 0) { }
        part = g_bsum[tid];
    }
    __syncthreads();           // everyone past spins before smem reuse
    if (tid < 128) s[tid] = part;
    __syncthreads();
    #pragma unroll
    for (int off = 64; off > 0; off >>= 1) {
        if (tid < off) s[tid] += s[tid + off];
        __syncthreads();
    }
    if (tid == 0) prev_s = s[0];
    __syncthreads();

    if (idx < N_NODES) {
        int o = prev_s + sum - v;
        g_off[idx] = o;
        g_cur[idx] = o;
    }
    if (idx == 0) g_off[N_NODES] = E_TOT;
}

// ---------------- scatter (profiled this round: capture slot 3) --------------
__global__ void scatter_kernel(const int* __restrict__ ei) {
    int e = blockIdx.x * blockDim.x + threadIdx.x;
    if (e >= E_TOT) return;
    int s, d;
    if (e < N_EDGES) {
        s = clampi(ei[e], 0, N_NODES - 1);
        d = clampi(ei[N_EDGES + e], 0, N_NODES - 1);
    } else {
        s = d = e - N_EDGES;
    }
    int pos = atomicAdd(&g_cur[d], 1);
    g_csr[pos] = s;
}

// ---------------- HMMA GEMM (R9 config: 32x32 warp tiles, ldmatrix) ----------
#define KCH    32
#define KW     (KCH / 2)
#define PADW   20

static __device__ __forceinline__ void mma_bf16(
    float& c0, float& c1, float& c2, float& c3,
    unsigned a0, unsigned a1, unsigned a2, unsigned a3,
    unsigned b0, unsigned b1)
{
    asm volatile(
        "mma.sync.aligned.m16n8k16.row.col.f32.bf16.bf16.f32 "
        "{%0,%1,%2,%3}, {%4,%5,%6,%7}, {%8,%9}, {%0,%1,%2,%3};"
        : "+f"(c0), "+f"(c1), "+f"(c2), "+f"(c3)
        : "r"(a0), "r"(a1), "r"(a2), "r"(a3), "r"(b0), "r"(b1));
}

static __device__ __forceinline__ void ldsm_x4(
    unsigned& r0, unsigned& r1, unsigned& r2, unsigned& r3, const unsigned* p)
{
    uint32_t a = (uint32_t)__cvta_generic_to_shared(p);
    asm volatile(
        "ldmatrix.sync.aligned.m8n8.x4.shared.b16 {%0,%1,%2,%3}, [%4];"
        : "=r"(r0), "=r"(r1), "=r"(r2), "=r"(r3) : "r"(a));
}

__global__ __launch_bounds__(256) void mma_gemm_kernel(
    const float* __restrict__ bl, const float* __restrict__ br)
{
    __shared__ unsigned sAh[128 * PADW];
    __shared__ unsigned sAl[128 * PADW];
    __shared__ unsigned sBh[64 * PADW];
    __shared__ unsigned sBl[64 * PADW];

    const int tid  = threadIdx.x;
    const int wid  = tid >> 5;
    const int lane = tid & 31;
    const int cb   = blockIdx.x;
    const int tile = blockIdx.y;
    const int set  = cb / 3;
    const int nb   = cb % 3;
    const int row0 = tile * M_TILE;
    const int col0 = nb * 64;
    float* Y        = set ? g_xr : g_xl;
    const float* bv = set ? br : bl;

    const int warp_m = (wid & 3) * 32;
    const int warp_n = (wid >> 2) * 32;
    const int lq = lane >> 2;
    const int lr = lane & 3;

    const int arow = lane & 15;
    const int akw  = (lane >> 4) << 2;
    const int brow = ((lane >> 4) << 3) + (lane & 7);
    const int bkw  = (lane & 8) ? 4 : 0;

    float acc[2][4][4];
    #pragma unroll
    for (int mi = 0; mi < 2; mi++)
        #pragma unroll
        for (int ni = 0; ni < 4; ni++)
            #pragma unroll
            for (int q = 0; q < 4; q++) acc[mi][ni][q] = 0.f;

    #pragma unroll 1
    for (int ch = 0; ch < IN_DIM / KCH; ch++) {
        #pragma unroll
        for (int jj = 0; jj < 2; jj++) {
            int j  = tid + jj * 256;
            int r  = j >> 2, kw = (j & 3) << 2;
            size_t src = (size_t)(row0 + r) * (IN_DIM / 2) + ch * KW + kw;
            *(uint4*)&sAh[r * PADW + kw] = *(const uint4*)&g_ahw[src];
            *(uint4*)&sAl[r * PADW + kw] = *(const uint4*)&g_alw[src];
        }
        {
            int r = tid >> 2, kw = (tid & 3) << 2;
            size_t src = (size_t)(set * OUTC + col0 + r) * (IN_DIM / 2) + ch * KW + kw;
            *(uint4*)&sBh[r * PADW + kw] = *(const uint4*)&g_bhw[src];
            *(uint4*)&sBl[r * PADW + kw] = *(const uint4*)&g_blw[src];
        }
        __syncthreads();

        #pragma unroll
        for (int ks = 0; ks < 2; ks++) {
            unsigned ah[2][4], al[2][4], bhp[2][4], blp[2][4];
            #pragma unroll
            for (int mi = 0; mi < 2; mi++) {
                int w = (warp_m + mi * 16 + arow) * PADW + ks * 8 + akw;
                ldsm_x4(ah[mi][0], ah[mi][1], ah[mi][2], ah[mi][3], &sAh[w]);
                ldsm_x4(al[mi][0], al[mi][1], al[mi][2], al[mi][3], &sAl[w]);
            }
            #pragma unroll
            for (int p = 0; p < 2; p++) {
                int w = (warp_n + p * 16 + brow) * PADW + ks * 8 + bkw;
                ldsm_x4(bhp[p][0], bhp[p][1], bhp[p][2], bhp[p][3], &sBh[w]);
                ldsm_x4(blp[p][0], blp[p][1], blp[p][2], blp[p][3], &sBl[w]);
            }
            #pragma unroll
            for (int mi = 0; mi < 2; mi++)
                #pragma unroll
                for (int ni = 0; ni < 4; ni++) {
                    float* c = acc[mi][ni];
                    unsigned b0 = bhp[ni >> 1][(ni & 1) * 2];
                    unsigned b1 = bhp[ni >> 1][(ni & 1) * 2 + 1];
                    unsigned l0 = blp[ni >> 1][(ni & 1) * 2];
                    unsigned l1 = blp[ni >> 1][(ni & 1) * 2 + 1];
                    mma_bf16(c[0], c[1], c[2], c[3],
                             ah[mi][0], ah[mi][1], ah[mi][2], ah[mi][3], b0, b1);
                    mma_bf16(c[0], c[1], c[2], c[3],
                             ah[mi][0], ah[mi][1], ah[mi][2], ah[mi][3], l0, l1);
                    mma_bf16(c[0], c[1], c[2], c[3],
                             al[mi][0], al[mi][1], al[mi][2], al[mi][3], b0, b1);
                }
        }
        __syncthreads();
    }

    #pragma unroll
    for (int ni = 0; ni < 4; ni++) {
        int c = col0 + warp_n + ni * 8 + lr * 2;
        float b0 = bv[c], b1 = bv[c + 1];
        #pragma unroll
        for (int mi = 0; mi < 2; mi++) {
            int r_lo = row0 + warp_m + mi * 16 + lq;
            int r_hi = r_lo + 8;
            float* ac = acc[mi][ni];
            if (r_lo < N_NODES) {
                float2 o = make_float2(ac[0] + b0, ac[1] + b1);
                *(float2*)(Y + (size_t)r_lo * OUTC + c) = o;
            }
            if (r_hi < N_NODES) {
                float2 o = make_float2(ac[2] + b0, ac[3] + b1);
                *(float2*)(Y + (size_t)r_hi * OUTC + c) = o;
            }
        }
    }
}

// ---------------- GATv2 aggregation: 2 nodes/warp, 16 lanes/node, no-max -----
__global__ __launch_bounds__(256) void agg_kernel(
    const float* __restrict__ att, const float* __restrict__ bias,
    float* __restrict__ out_fc, float* __restrict__ out_pre)
{
    const int warp = (blockIdx.x * blockDim.x + threadIdx.x) >> 5;
    const int lane = threadIdx.x & 31;
    const int half = lane >> 4;
    const int sl   = lane & 15;
    const int i    = warp * 2 + half;
    const bool nv  = (i < N_NODES);

    float xr_[12], attv[12], acc[12];
    float dnm[3] = {0.f, 0.f, 0.f};
    #pragma unroll
    for (int k = 0; k < 12; k++) {
        xr_[k]  = nv ? g_xr[i * OUTC + sl + 16 * k] : 0.f;
        attv[k] = __ldg(&att[sl + 16 * k]);
        acc[k]  = 0.f;
    }

    const int beg = nv ? g_off[i] : 0;
    const int deg = nv ? (g_off[i + 1] - beg) : 0;
    const int odeg = __shfl_xor_sync(0xffffffffu, deg, 16);
    const int md = (deg > odeg) ? deg : odeg;

    for (int idx = 0; idx < md; idx++) {
        const bool valid = idx < deg;
        const int src = valid ? __ldg(&g_csr[beg + idx]) : 0;
        float xs[12];
        float p0 = 0.f, p1 = 0.f, p2 = 0.f;
        #pragma unroll
        for (int k = 0; k < 12; k++) {
            xs[k] = g_xl[src * OUTC + sl + 16 * k];
            float t = xs[k] + xr_[k];
            t = fmaxf(t, 0.2f * t);            // leaky_relu 0.2
            t *= attv[k];
            if (k < 4) p0 += t; else if (k < 8) p1 += t; else p2 += t;
        }
        #pragma unroll
        for (int off = 8; off > 0; off >>= 1) {
            p0 += __shfl_xor_sync(0xffffffffu, p0, off);
            p1 += __shfl_xor_sync(0xffffffffu, p1, off);
            p2 += __shfl_xor_sync(0xffffffffu, p2, off);
        }
        float w0 = valid ? __expf(p0) : 0.f;
        float w1 = valid ? __expf(p1) : 0.f;
        float w2 = valid ? __expf(p2) : 0.f;
        dnm[0] += w0; dnm[1] += w1; dnm[2] += w2;
        float wh[3] = {w0, w1, w2};
        #pragma unroll
        for (int k = 0; k < 12; k++)
            acc[k] = fmaf(wh[k >> 2], xs[k], acc[k]);
    }

    if (nv) {
        float inv[3];
        #pragma unroll
        for (int h = 0; h < 3; h++) inv[h] = 1.f / dnm[h];
        #pragma unroll
        for (int k = 0; k < 12; k++) {
            int c = sl + 16 * k;
            float o = acc[k] * inv[k >> 2] + bias[c];
            out_fc[i * OUTC + c] = o;
            out_pre[i * OUTC + c] = (o > 0.f) ? o : 0.01f * o;  // leaky 0.01
        }
    }
}

// ---------------- mean pool v2: grid (64 graphs, 6 col-chunks) ---------------
__global__ __launch_bounds__(256) void pool_kernel(
    const int* __restrict__ batch,
    const float* __restrict__ pre, float* __restrict__ post)
{
    const int g     = blockIdx.x;
    const int chunk = blockIdx.y;
    const int tid   = threadIdx.x;
    const int cl    = tid & 31;          // col within chunk
    const int rs    = tid >> 5;          // row slice 0..7
    const int c     = chunk * 32 + cl;

    __shared__ int sbeg, send;
    __shared__ float red[8][33];
    if (tid < 2) {
        int target = g + tid;
        int lo = 0, hi = N_NODES;
        while (lo < hi) {
            int mid = (lo + hi) >> 1;
            if (batch[mid] < target) lo = mid + 1; else hi = mid;
        }
        if (tid == 0) sbeg = lo; else send = lo;
    }
    __syncthreads();

    float sum = 0.f;
    for (int r = sbeg + rs; r < send; r += 8)
        sum += pre[(size_t)r * OUTC + c];
    red[rs][cl] = sum;
    __syncthreads();
    if (rs == 0) {
        float tot = red[0][cl] + red[1][cl] + red[2][cl] + red[3][cl]
                  + red[4][cl] + red[5][cl] + red[6][cl] + red[7][cl];
        float cnt = (float)(send - sbeg);
        post[g * OUTC + c] = tot / fmaxf(cnt, 1.f);
    }
}

// ---------------- classifier -------------------------------------------------
__global__ void cls_kernel(const float* __restrict__ post,
                           const float* __restrict__ Wc,
                           const float* __restrict__ bc,
                           float* __restrict__ logits)
{
    int t = blockIdx.x * blockDim.x + threadIdx.x;
    if (t >= NUM_GRAPHS * NUM_CLASSES) return;
    int g = t / NUM_CLASSES, c = t % NUM_CLASSES;
    float s = bc[c];
    #pragma unroll 8
    for (int k = 0; k < OUTC; k++)
        s = fmaf(post[g * OUTC + k], Wc[k * NUM_CLASSES + c], s);
    logits[g * NUM_CLASSES + c] = s;
}

// ---------------- launch -----------------------------------------------------
extern "C" void kernel_launch(void* const* d_in, const int* in_sizes, int n_in,
                              void* d_out, int out_size)
{
    const float* x     = (const float*)d_in[0];
    const int*   ei    = (const int*)d_in[1];
    const int*   batch = (const int*)d_in[2];
    const float* Wl   = (const float*)d_in[3];
    const float* bl   = (const float*)d_in[4];
    const float* Wr   = (const float*)d_in[5];
    const float* br   = (const float*)d_in[6];
    const float* att  = (const float*)d_in[7];
    const float* bias = (const float*)d_in[8];
    const float* Wc   = (const float*)d_in[9];
    const float* bc   = (const float*)d_in[10];

    float* out        = (float*)d_out;
    float* out_logits = out;
    float* out_pre    = out + NUM_GRAPHS * NUM_CLASSES;
    float* out_post   = out_pre + (size_t)N_NODES * OUTC;
    float* out_fc     = out_post + NUM_GRAPHS * OUTC;

    // 0: fused prep (x/W decomposition + deg/flag zero)
    fused_prep_kernel<<<FUSED_BLOCKS, 256>>>(x, Wl, Wr);
    // 1: degree count
    deg_count_kernel<<<(N_EDGES + 255) / 256, 256>>>(ei);
    // 2: single-kernel scan (all 98 blocks resident -> safe spin)
    scan_kernel<<<N_SBLKS, SCAN_BLK>>>();
    // 3: scatter  <- profiled (capture slot 3)
    scatter_kernel<<<(E_TOT + 255) / 256, 256>>>(ei);
    // 4: tensor-core GEMM
    mma_gemm_kernel<<<dim3(6, N_TILES_M), 256>>>(bl, br);
    // 5: aggregation
    agg_kernel<<<(N_NODES / 2 * 32 + 255) / 256, 256>>>(att, bias, out_fc, out_pre);
    // 6: mean pool (parallel)
    pool_kernel<<<dim3(NUM_GRAPHS, 6), 256>>>(batch, out_pre, out_post);
    // 7: classifier
    cls_kernel<<<1, NUM_GRAPHS * NUM_CLASSES>>>(out_post, Wc, bc, out_logits);
}

// round 14
// speedup vs baseline: 1.4106x; 1.4106x over previous
#include <cuda_runtime.h>
#include <cuda_bf16.h>
#include <cstdint>
#include <math.h>

#define N_NODES   100000
#define N_EDGES   1600000
#define E_TOT     (N_EDGES + N_NODES)
#define IN_DIM    256
#define HID       64
#define HEADS     3
#define OUTC      (HEADS * HID)         // 192
#define NUM_CLASSES 10
#define NUM_GRAPHS  64

#define SCAN_BLK  1024
#define N_SBLKS   ((N_NODES + SCAN_BLK - 1) / SCAN_BLK)   // 98

#define M_TILE    128
#define N_TILES_M 782                   // ceil(100000/128)
#define ROWS_PAD  (N_TILES_M * M_TILE)  // 100096

// ---------------- scratch ----------------------------------------------------
__device__ float g_xl[N_NODES * OUTC];
__device__ float g_xr[N_NODES * OUTC];
__device__ int   g_deg[N_NODES + 1];
__device__ int   g_off[N_NODES + 1];
__device__ int   g_cur[N_NODES];
__device__ int   g_csr[E_TOT];
__device__ int   g_bsum[N_SBLKS];
__device__ int   g_boff[N_SBLKS];
// decomposed operands: packed bf16 pairs (k, k+1) as uint32 words
__device__ __align__(16) unsigned g_ahw[ROWS_PAD * (IN_DIM / 2)];       // hi(x)
__device__ __align__(16) unsigned g_alw[ROWS_PAD * (IN_DIM / 2)];       // lo(x)
__device__ __align__(16) unsigned g_bhw[2 * OUTC * (IN_DIM / 2)];       // hi(W^T)
__device__ __align__(16) unsigned g_blw[2 * OUTC * (IN_DIM / 2)];       // lo(W^T)

static __device__ __forceinline__ int clampi(int v, int lo, int hi) {
    return v < lo ? lo : (v > hi ? hi : v);
}

static __device__ __forceinline__ unsigned pack_bf16(unsigned short a, unsigned short b) {
    return (unsigned)a | ((unsigned)b << 16);
}

static __device__ __forceinline__ void split_bf16(float f, unsigned short& h, unsigned short& l) {
    __nv_bfloat16 hb = __float2bfloat16(f);
    __nv_bfloat16 lb = __float2bfloat16(f - __bfloat162float(hb));
    h = __bfloat16_as_ushort(hb);
    l = __bfloat16_as_ushort(lb);
}

// ---------------- prep A: x -> hi/lo bf16 packed row-major -------------------
__global__ __launch_bounds__(256) void prep_a_kernel(const float* __restrict__ x)
{
    int t = blockIdx.x * blockDim.x + threadIdx.x;
    if (t >= ROWS_PAD * 64) return;
    int k4  = t & 63;
    int row = t >> 6;
    float4 v = make_float4(0.f, 0.f, 0.f, 0.f);
    if (row < N_NODES) v = *(const float4*)(x + (size_t)row * IN_DIM + k4 * 4);
    float f[4] = {v.x, v.y, v.z, v.w};
    unsigned short h[4], l[4];
    #pragma unroll
    for (int j = 0; j < 4; j++) split_bf16(f[j], h[j], l[j]);
    int base = row * (IN_DIM / 2) + k4 * 2;
    g_ahw[base]     = pack_bf16(h[0], h[1]);
    g_ahw[base + 1] = pack_bf16(h[2], h[3]);
    g_alw[base]     = pack_bf16(l[0], l[1]);
    g_alw[base + 1] = pack_bf16(l[2], l[3]);
}

// ---------------- prep B: W[k][n] -> B^T[n][k] hi/lo bf16 packed -------------
__global__ __launch_bounds__(256) void prep_b_kernel(
    const float* __restrict__ Wl, const float* __restrict__ Wr)
{
    int t = blockIdx.x * blockDim.x + threadIdx.x;
    if (t >= 2 * OUTC * 64) return;
    int k4 = t & 63;
    int n  = (t >> 6) % OUTC;
    int s  = t / (OUTC * 64);
    const float* W = s ? Wr : Wl;
    float f[4];
    #pragma unroll
    for (int j = 0; j < 4; j++) f[j] = W[(size_t)(k4 * 4 + j) * OUTC + n];
    unsigned short h[4], l[4];
    #pragma unroll
    for (int j = 0; j < 4; j++) split_bf16(f[j], h[j], l[j]);
    int base = (s * OUTC + n) * (IN_DIM / 2) + k4 * 2;
    g_bhw[base]     = pack_bf16(h[0], h[1]);
    g_bhw[base + 1] = pack_bf16(h[2], h[3]);
    g_blw[base]     = pack_bf16(l[0], l[1]);
    g_blw[base + 1] = pack_bf16(l[2], l[3]);
}

// ---------------- HMMA GEMM (R9 config: 32x32 warp tiles, ldmatrix) ----------
#define KCH    32
#define KW     (KCH / 2)                 // 16 words per row per chunk
#define PADW   20                        // padded row stride in words

static __device__ __forceinline__ void mma_bf16(
    float& c0, float& c1, float& c2, float& c3,
    unsigned a0, unsigned a1, unsigned a2, unsigned a3,
    unsigned b0, unsigned b1)
{
    asm volatile(
        "mma.sync.aligned.m16n8k16.row.col.f32.bf16.bf16.f32 "
        "{%0,%1,%2,%3}, {%4,%5,%6,%7}, {%8,%9}, {%0,%1,%2,%3};"
        : "+f"(c0), "+f"(c1), "+f"(c2), "+f"(c3)
        : "r"(a0), "r"(a1), "r"(a2), "r"(a3), "r"(b0), "r"(b1));
}

static __device__ __forceinline__ void ldsm_x4(
    unsigned& r0, unsigned& r1, unsigned& r2, unsigned& r3, const unsigned* p)
{
    uint32_t a = (uint32_t)__cvta_generic_to_shared(p);
    asm volatile(
        "ldmatrix.sync.aligned.m8n8.x4.shared.b16 {%0,%1,%2,%3}, [%4];"
        : "=r"(r0), "=r"(r1), "=r"(r2), "=r"(r3) : "r"(a));
}

__global__ __launch_bounds__(256) void mma_gemm_kernel(
    const float* __restrict__ bl, const float* __restrict__ br)
{
    __shared__ unsigned sAh[128 * PADW];
    __shared__ unsigned sAl[128 * PADW];
    __shared__ unsigned sBh[64 * PADW];
    __shared__ unsigned sBl[64 * PADW];

    const int tid  = threadIdx.x;
    const int wid  = tid >> 5;
    const int lane = tid & 31;
    const int cb   = blockIdx.x;
    const int tile = blockIdx.y;
    const int set  = cb / 3;
    const int nb   = cb % 3;
    const int row0 = tile * M_TILE;
    const int col0 = nb * 64;
    float* Y        = set ? g_xr : g_xl;
    const float* bv = set ? br : bl;

    const int warp_m = (wid & 3) * 32;
    const int warp_n = (wid >> 2) * 32;
    const int lq = lane >> 2;
    const int lr = lane & 3;

    const int arow = lane & 15;
    const int akw  = (lane >> 4) << 2;
    const int brow = ((lane >> 4) << 3) + (lane & 7);
    const int bkw  = (lane & 8) ? 4 : 0;

    float acc[2][4][4];
    #pragma unroll
    for (int mi = 0; mi < 2; mi++)
        #pragma unroll
        for (int ni = 0; ni < 4; ni++)
            #pragma unroll
            for (int q = 0; q < 4; q++) acc[mi][ni][q] = 0.f;

    #pragma unroll 1
    for (int ch = 0; ch < IN_DIM / KCH; ch++) {
        #pragma unroll
        for (int jj = 0; jj < 2; jj++) {
            int j  = tid + jj * 256;
            int r  = j >> 2, kw = (j & 3) << 2;
            size_t src = (size_t)(row0 + r) * (IN_DIM / 2) + ch * KW + kw;
            *(uint4*)&sAh[r * PADW + kw] = *(const uint4*)&g_ahw[src];
            *(uint4*)&sAl[r * PADW + kw] = *(const uint4*)&g_alw[src];
        }
        {
            int r = tid >> 2, kw = (tid & 3) << 2;
            size_t src = (size_t)(set * OUTC + col0 + r) * (IN_DIM / 2) + ch * KW + kw;
            *(uint4*)&sBh[r * PADW + kw] = *(const uint4*)&g_bhw[src];
            *(uint4*)&sBl[r * PADW + kw] = *(const uint4*)&g_blw[src];
        }
        __syncthreads();

        #pragma unroll
        for (int ks = 0; ks < 2; ks++) {
            unsigned ah[2][4], al[2][4], bhp[2][4], blp[2][4];
            #pragma unroll
            for (int mi = 0; mi < 2; mi++) {
                int w = (warp_m + mi * 16 + arow) * PADW + ks * 8 + akw;
                ldsm_x4(ah[mi][0], ah[mi][1], ah[mi][2], ah[mi][3], &sAh[w]);
                ldsm_x4(al[mi][0], al[mi][1], al[mi][2], al[mi][3], &sAl[w]);
            }
            #pragma unroll
            for (int p = 0; p < 2; p++) {
                int w = (warp_n + p * 16 + brow) * PADW + ks * 8 + bkw;
                ldsm_x4(bhp[p][0], bhp[p][1], bhp[p][2], bhp[p][3], &sBh[w]);
                ldsm_x4(blp[p][0], blp[p][1], blp[p][2], blp[p][3], &sBl[w]);
            }
            #pragma unroll
            for (int mi = 0; mi < 2; mi++)
                #pragma unroll
                for (int ni = 0; ni < 4; ni++) {
                    float* c = acc[mi][ni];
                    unsigned b0 = bhp[ni >> 1][(ni & 1) * 2];
                    unsigned b1 = bhp[ni >> 1][(ni & 1) * 2 + 1];
                    unsigned l0 = blp[ni >> 1][(ni & 1) * 2];
                    unsigned l1 = blp[ni >> 1][(ni & 1) * 2 + 1];
                    mma_bf16(c[0], c[1], c[2], c[3],
                             ah[mi][0], ah[mi][1], ah[mi][2], ah[mi][3], b0, b1);
                    mma_bf16(c[0], c[1], c[2], c[3],
                             ah[mi][0], ah[mi][1], ah[mi][2], ah[mi][3], l0, l1);
                    mma_bf16(c[0], c[1], c[2], c[3],
                             al[mi][0], al[mi][1], al[mi][2], al[mi][3], b0, b1);
                }
        }
        __syncthreads();
    }

    #pragma unroll
    for (int ni = 0; ni < 4; ni++) {
        int c = col0 + warp_n + ni * 8 + lr * 2;
        float b0 = bv[c], b1 = bv[c + 1];
        #pragma unroll
        for (int mi = 0; mi < 2; mi++) {
            int r_lo = row0 + warp_m + mi * 16 + lq;
            int r_hi = r_lo + 8;
            float* ac = acc[mi][ni];
            if (r_lo < N_NODES) {
                float2 o = make_float2(ac[0] + b0, ac[1] + b1);
                *(float2*)(Y + (size_t)r_lo * OUTC + c) = o;
            }
            if (r_hi < N_NODES) {
                float2 o = make_float2(ac[2] + b0, ac[3] + b1);
                *(float2*)(Y + (size_t)r_hi * OUTC + c) = o;
            }
        }
    }
}

// ---------------- CSR construction ------------------------------------------
__global__ void deg_init_kernel() {
    int i = blockIdx.x * blockDim.x + threadIdx.x;
    if (i < N_NODES) g_deg[i] = 1;
}

__global__ void deg_count_kernel(const int* __restrict__ ei) {
    int e = blockIdx.x * blockDim.x + threadIdx.x;
    if (e < N_EDGES) {
        int d = clampi(ei[N_EDGES + e], 0, N_NODES - 1);
        atomicAdd(&g_deg[d], 1);
    }
}

__global__ __launch_bounds__(SCAN_BLK) void scan_local_kernel() {
    __shared__ int s[SCAN_BLK];
    const int tid = threadIdx.x;
    const int idx = blockIdx.x * SCAN_BLK + tid;
    int v = (idx < N_NODES) ? g_deg[idx] : 0;
    int sum = v;
    #pragma unroll
    for (int off = 1; off < SCAN_BLK; off <<= 1) {
        s[tid] = sum;
        __syncthreads();
        if (tid >= off) sum += s[tid - off];
        __syncthreads();
    }
    if (idx < N_NODES) g_off[idx] = sum - v;
    if (tid == SCAN_BLK - 1) g_bsum[blockIdx.x] = sum;
}

__global__ __launch_bounds__(128) void scan_bsum_kernel() {
    __shared__ int s[128];
    const int tid = threadIdx.x;
    int v = (tid < N_SBLKS) ? g_bsum[tid] : 0;
    int sum = v;
    #pragma unroll
    for (int off = 1; off < 128; off <<= 1) {
        s[tid] = sum;
        __syncthreads();
        if (tid >= off) sum += s[tid - off];
        __syncthreads();
    }
    if (tid < N_SBLKS) g_boff[tid] = sum - v;
}

__global__ __launch_bounds__(SCAN_BLK) void scan_add_kernel() {
    const int idx = blockIdx.x * SCAN_BLK + threadIdx.x;
    if (idx < N_NODES) {
        int o = g_off[idx] + g_boff[blockIdx.x];
        g_off[idx] = o;
        g_cur[idx] = o;
    }
    if (idx == 0) g_off[N_NODES] = E_TOT;
}

__global__ void scatter_kernel(const int* __restrict__ ei) {
    int e = blockIdx.x * blockDim.x + threadIdx.x;
    if (e >= E_TOT) return;
    int s, d;
    if (e < N_EDGES) {
        s = clampi(ei[e], 0, N_NODES - 1);
        d = clampi(ei[N_EDGES + e], 0, N_NODES - 1);
    } else {
        s = d = e - N_EDGES;
    }
    int pos = atomicAdd(&g_cur[d], 1);
    g_csr[pos] = s;
}

// ---------------- GATv2 aggregation: 2 nodes/warp, 16 lanes/node, no-max -----
__global__ __launch_bounds__(256) void agg_kernel(
    const float* __restrict__ att, const float* __restrict__ bias,
    float* __restrict__ out_fc, float* __restrict__ out_pre)
{
    const int warp = (blockIdx.x * blockDim.x + threadIdx.x) >> 5;
    const int lane = threadIdx.x & 31;
    const int half = lane >> 4;
    const int sl   = lane & 15;
    const int i    = warp * 2 + half;
    const bool nv  = (i < N_NODES);

    float xr_[12], attv[12], acc[12];
    float dnm[3] = {0.f, 0.f, 0.f};
    #pragma unroll
    for (int k = 0; k < 12; k++) {
        xr_[k]  = nv ? g_xr[i * OUTC + sl + 16 * k] : 0.f;
        attv[k] = __ldg(&att[sl + 16 * k]);
        acc[k]  = 0.f;
    }

    const int beg = nv ? g_off[i] : 0;
    const int deg = nv ? (g_off[i + 1] - beg) : 0;
    const int odeg = __shfl_xor_sync(0xffffffffu, deg, 16);
    const int md = (deg > odeg) ? deg : odeg;

    for (int idx = 0; idx < md; idx++) {
        const bool valid = idx < deg;
        const int src = valid ? __ldg(&g_csr[beg + idx]) : 0;
        float xs[12];
        float p0 = 0.f, p1 = 0.f, p2 = 0.f;
        #pragma unroll
        for (int k = 0; k < 12; k++) {
            xs[k] = g_xl[src * OUTC + sl + 16 * k];
            float t = xs[k] + xr_[k];
            t = fmaxf(t, 0.2f * t);            // leaky_relu 0.2
            t *= attv[k];
            if (k < 4) p0 += t; else if (k < 8) p1 += t; else p2 += t;
        }
        #pragma unroll
        for (int off = 8; off > 0; off >>= 1) {
            p0 += __shfl_xor_sync(0xffffffffu, p0, off);
            p1 += __shfl_xor_sync(0xffffffffu, p1, off);
            p2 += __shfl_xor_sync(0xffffffffu, p2, off);
        }
        float w0 = valid ? __expf(p0) : 0.f;
        float w1 = valid ? __expf(p1) : 0.f;
        float w2 = valid ? __expf(p2) : 0.f;
        dnm[0] += w0; dnm[1] += w1; dnm[2] += w2;
        float wh[3] = {w0, w1, w2};
        #pragma unroll
        for (int k = 0; k < 12; k++)
            acc[k] = fmaf(wh[k >> 2], xs[k], acc[k]);
    }

    if (nv) {
        float inv[3];
        #pragma unroll
        for (int h = 0; h < 3; h++) inv[h] = 1.f / dnm[h];
        #pragma unroll
        for (int k = 0; k < 12; k++) {
            int c = sl + 16 * k;
            float o = acc[k] * inv[k >> 2] + bias[c];
            out_fc[i * OUTC + c] = o;
            out_pre[i * OUTC + c] = (o > 0.f) ? o : 0.01f * o;  // leaky 0.01
        }
    }
}

// ---------------- mean pool v2: grid (64 graphs, 6 col-chunks) ---------------
__global__ __launch_bounds__(256) void pool_kernel(
    const int* __restrict__ batch,
    const float* __restrict__ pre, float* __restrict__ post)
{
    const int g     = blockIdx.x;
    const int chunk = blockIdx.y;
    const int tid   = threadIdx.x;
    const int cl    = tid & 31;          // col within chunk
    const int rs    = tid >> 5;          // row slice 0..7
    const int c     = chunk * 32 + cl;

    __shared__ int sbeg, send;
    __shared__ float red[8][33];
    if (tid < 2) {
        int target = g + tid;
        int lo = 0, hi = N_NODES;
        while (lo < hi) {
            int mid = (lo + hi) >> 1;
            if (batch[mid] < target) lo = mid + 1; else hi = mid;
        }
        if (tid == 0) sbeg = lo; else send = lo;
    }
    __syncthreads();

    float sum = 0.f;
    for (int r = sbeg + rs; r < send; r += 8)
        sum += pre[(size_t)r * OUTC + c];
    red[rs][cl] = sum;
    __syncthreads();
    if (rs == 0) {
        float tot = red[0][cl] + red[1][cl] + red[2][cl] + red[3][cl]
                  + red[4][cl] + red[5][cl] + red[6][cl] + red[7][cl];
        float cnt = (float)(send - sbeg);
        post[g * OUTC + c] = tot / fmaxf(cnt, 1.f);
    }
}

// ---------------- classifier -------------------------------------------------
__global__ void cls_kernel(const float* __restrict__ post,
                           const float* __restrict__ Wc,
                           const float* __restrict__ bc,
                           float* __restrict__ logits)
{
    int t = blockIdx.x * blockDim.x + threadIdx.x;
    if (t >= NUM_GRAPHS * NUM_CLASSES) return;
    int g = t / NUM_CLASSES, c = t % NUM_CLASSES;
    float s = bc[c];
    #pragma unroll 8
    for (int k = 0; k < OUTC; k++)
        s = fmaf(post[g * OUTC + k], Wc[k * NUM_CLASSES + c], s);
    logits[g * NUM_CLASSES + c] = s;
}

// ---------------- launch -----------------------------------------------------
extern "C" void kernel_launch(void* const* d_in, const int* in_sizes, int n_in,
                              void* d_out, int out_size)
{
    const float* x     = (const float*)d_in[0];
    const int*   ei    = (const int*)d_in[1];
    const int*   batch = (const int*)d_in[2];
    const float* Wl   = (const float*)d_in[3];
    const float* bl   = (const float*)d_in[4];
    const float* Wr   = (const float*)d_in[5];
    const float* br   = (const float*)d_in[6];
    const float* att  = (const float*)d_in[7];
    const float* bias = (const float*)d_in[8];
    const float* Wc   = (const float*)d_in[9];
    const float* bc   = (const float*)d_in[10];

    float* out        = (float*)d_out;
    float* out_logits = out;
    float* out_pre    = out + NUM_GRAPHS * NUM_CLASSES;
    float* out_post   = out_pre + (size_t)N_NODES * OUTC;
    float* out_fc     = out_post + NUM_GRAPHS * OUTC;

    // 1-2: operand decomposition
    prep_a_kernel<<<(ROWS_PAD * 64 + 255) / 256, 256>>>(x);
    prep_b_kernel<<<(2 * OUTC * 64 + 255) / 256, 256>>>(Wl, Wr);
    // 3: CSR init (independent)
    deg_init_kernel<<<(N_NODES + 255) / 256, 256>>>();
    // 4: tensor-core GEMM (R9 config)
    mma_gemm_kernel<<<dim3(6, N_TILES_M), 256>>>(bl, br);
    // 5+: CSR build (3-phase scan, proven fast)
    deg_count_kernel<<<(N_EDGES + 255) / 256, 256>>>(ei);
    scan_local_kernel<<<N_SBLKS, SCAN_BLK>>>();
    scan_bsum_kernel<<<1, 128>>>();
    scan_add_kernel<<<N_SBLKS, SCAN_BLK>>>();
    scatter_kernel<<<(E_TOT + 255) / 256, 256>>>(ei);
    // aggregation: 2 nodes per warp, exp without max-shift
    agg_kernel<<<(N_NODES / 2 * 32 + 255) / 256, 256>>>(att, bias, out_fc, out_pre);
    // mean pool (parallel v2) + classifier
    pool_kernel<<<dim3(NUM_GRAPHS, 6), 256>>>(batch, out_pre, out_post);
    cls_kernel<<<1, NUM_GRAPHS * NUM_CLASSES>>>(out_post, Wc, bc, out_logits);
}

// round 15
// speedup vs baseline: 1.5037x; 1.0660x over previous
#include <cuda_runtime.h>
#include <cuda_bf16.h>
#include <cstdint>
#include <math.h>

#define N_NODES   100000
#define N_EDGES   1600000
#define E_TOT     (N_EDGES + N_NODES)
#define IN_DIM    256
#define HID       64
#define HEADS     3
#define OUTC      (HEADS * HID)         // 192
#define NUM_CLASSES 10
#define NUM_GRAPHS  64

#define SCAN_BLK  1024
#define N_SBLKS   ((N_NODES + SCAN_BLK - 1) / SCAN_BLK)   // 98

#define M_TILE    128
#define N_TILES_M 782                   // ceil(100000/128)
#define ROWS_PAD  (N_TILES_M * M_TILE)  // 100096

// ---------------- scratch ----------------------------------------------------
__device__ float g_xl[N_NODES * OUTC];
__device__ float g_xr[N_NODES * OUTC];
__device__ int   g_deg[N_NODES + 1];
__device__ int   g_off[N_NODES + 1];
__device__ int   g_cur[N_NODES];
__device__ int   g_csr[E_TOT];
__device__ int   g_bsum[N_SBLKS];
__device__ int   g_boff[N_SBLKS];
// decomposed operands: packed bf16 pairs (k, k+1) as uint32 words
__device__ __align__(16) unsigned g_ahw[ROWS_PAD * (IN_DIM / 2)];       // hi(x)
__device__ __align__(16) unsigned g_alw[ROWS_PAD * (IN_DIM / 2)];       // lo(x)
__device__ __align__(16) unsigned g_bhw[2 * OUTC * (IN_DIM / 2)];       // hi(W^T)
__device__ __align__(16) unsigned g_blw[2 * OUTC * (IN_DIM / 2)];       // lo(W^T)

static __device__ __forceinline__ int clampi(int v, int lo, int hi) {
    return v < lo ? lo : (v > hi ? hi : v);
}

static __device__ __forceinline__ unsigned pack_bf16(unsigned short a, unsigned short b) {
    return (unsigned)a | ((unsigned)b << 16);
}

static __device__ __forceinline__ void split_bf16(float f, unsigned short& h, unsigned short& l) {
    __nv_bfloat16 hb = __float2bfloat16(f);
    __nv_bfloat16 lb = __float2bfloat16(f - __bfloat162float(hb));
    h = __bfloat16_as_ushort(hb);
    l = __bfloat16_as_ushort(lb);
}

// ---------------- prep A: x -> hi/lo bf16 packed row-major -------------------
__global__ __launch_bounds__(256) void prep_a_kernel(const float* __restrict__ x)
{
    int t = blockIdx.x * blockDim.x + threadIdx.x;
    if (t >= ROWS_PAD * 64) return;
    int k4  = t & 63;
    int row = t >> 6;
    float4 v = make_float4(0.f, 0.f, 0.f, 0.f);
    if (row < N_NODES) v = *(const float4*)(x + (size_t)row * IN_DIM + k4 * 4);
    float f[4] = {v.x, v.y, v.z, v.w};
    unsigned short h[4], l[4];
    #pragma unroll
    for (int j = 0; j < 4; j++) split_bf16(f[j], h[j], l[j]);
    int base = row * (IN_DIM / 2) + k4 * 2;
    g_ahw[base]     = pack_bf16(h[0], h[1]);
    g_ahw[base + 1] = pack_bf16(h[2], h[3]);
    g_alw[base]     = pack_bf16(l[0], l[1]);
    g_alw[base + 1] = pack_bf16(l[2], l[3]);
}

// ---------------- prep B: W[k][n] -> B^T[n][k] hi/lo bf16 packed -------------
__global__ __launch_bounds__(256) void prep_b_kernel(
    const float* __restrict__ Wl, const float* __restrict__ Wr)
{
    int t = blockIdx.x * blockDim.x + threadIdx.x;
    if (t >= 2 * OUTC * 64) return;
    int k4 = t & 63;
    int n  = (t >> 6) % OUTC;
    int s  = t / (OUTC * 64);
    const float* W = s ? Wr : Wl;
    float f[4];
    #pragma unroll
    for (int j = 0; j < 4; j++) f[j] = W[(size_t)(k4 * 4 + j) * OUTC + n];
    unsigned short h[4], l[4];
    #pragma unroll
    for (int j = 0; j < 4; j++) split_bf16(f[j], h[j], l[j]);
    int base = (s * OUTC + n) * (IN_DIM / 2) + k4 * 2;
    g_bhw[base]     = pack_bf16(h[0], h[1]);
    g_bhw[base + 1] = pack_bf16(h[2], h[3]);
    g_blw[base]     = pack_bf16(l[0], l[1]);
    g_blw[base + 1] = pack_bf16(l[2], l[3]);
}

// ---------------- HMMA GEMM: cp.async double-buffered pipeline ---------------
#define KCH    32
#define KW     (KCH / 2)                 // 16 words per row per chunk
#define PADW   20                        // padded row stride in words
#define NCHUNK (IN_DIM / KCH)            // 8

#define A_W    (128 * PADW)              // 2560 words per A array
#define B_W    (64 * PADW)               // 1280 words per B array
#define AH_OFF 0
#define AL_OFF A_W
#define BH_OFF (2 * A_W)
#define BL_OFF (2 * A_W + B_W)
#define BUF_W  (2 * A_W + 2 * B_W)       // 7680 words per buffer
#define SMEM_GEMM_BYTES (2 * BUF_W * 4)  // 61440

static __device__ __forceinline__ void mma_bf16(
    float& c0, float& c1, float& c2, float& c3,
    unsigned a0, unsigned a1, unsigned a2, unsigned a3,
    unsigned b0, unsigned b1)
{
    asm volatile(
        "mma.sync.aligned.m16n8k16.row.col.f32.bf16.bf16.f32 "
        "{%0,%1,%2,%3}, {%4,%5,%6,%7}, {%8,%9}, {%0,%1,%2,%3};"
        : "+f"(c0), "+f"(c1), "+f"(c2), "+f"(c3)
        : "r"(a0), "r"(a1), "r"(a2), "r"(a3), "r"(b0), "r"(b1));
}

static __device__ __forceinline__ void ldsm_x4(
    unsigned& r0, unsigned& r1, unsigned& r2, unsigned& r3, const unsigned* p)
{
    uint32_t a = (uint32_t)__cvta_generic_to_shared(p);
    asm volatile(
        "ldmatrix.sync.aligned.m8n8.x4.shared.b16 {%0,%1,%2,%3}, [%4];"
        : "=r"(r0), "=r"(r1), "=r"(r2), "=r"(r3) : "r"(a));
}

static __device__ __forceinline__ void cp16(unsigned* sdst, const unsigned* gsrc)
{
    uint32_t sa = (uint32_t)__cvta_generic_to_shared(sdst);
    asm volatile("cp.async.cg.shared.global [%0], [%1], 16;"
                 :: "r"(sa), "l"(gsrc));
}

__global__ __launch_bounds__(256) void mma_gemm_kernel(
    const float* __restrict__ bl, const float* __restrict__ br)
{
    extern __shared__ unsigned dsm[];

    const int tid  = threadIdx.x;
    const int wid  = tid >> 5;
    const int lane = tid & 31;
    const int cb   = blockIdx.x;
    const int tile = blockIdx.y;
    const int set  = cb / 3;
    const int nb   = cb % 3;
    const int row0 = tile * M_TILE;
    const int col0 = nb * 64;
    float* Y        = set ? g_xr : g_xl;
    const float* bv = set ? br : bl;

    const int warp_m = (wid & 3) * 32;
    const int warp_n = (wid >> 2) * 32;
    const int lq = lane >> 2;
    const int lr = lane & 3;

    const int arow = lane & 15;
    const int akw  = (lane >> 4) << 2;
    const int brow = ((lane >> 4) << 3) + (lane & 7);
    const int bkw  = (lane & 8) ? 4 : 0;

    // fill addressing (constant across chunks)
    const int ar0 = tid >> 2,        akw0 = (tid & 3) << 2;         // A row for jj=0
    const int ar1 = (tid + 256) >> 2, akw1 = ((tid + 256) & 3) << 2; // A row for jj=1
    const int br_ = tid >> 2,        bkw0 = (tid & 3) << 2;         // B row

    float acc[2][4][4];
    #pragma unroll
    for (int mi = 0; mi < 2; mi++)
        #pragma unroll
        for (int ni = 0; ni < 4; ni++)
            #pragma unroll
            for (int q = 0; q < 4; q++) acc[mi][ni][q] = 0.f;

    // ---- async fill of chunk ch into buffer buf ----
    auto fill = [&](int ch, int buf) {
        unsigned* base = dsm + buf * BUF_W;
        size_t sA0 = (size_t)(row0 + ar0) * (IN_DIM / 2) + ch * KW + akw0;
        size_t sA1 = (size_t)(row0 + ar1) * (IN_DIM / 2) + ch * KW + akw1;
        cp16(base + AH_OFF + ar0 * PADW + akw0, &g_ahw[sA0]);
        cp16(base + AH_OFF + ar1 * PADW + akw1, &g_ahw[sA1]);
        cp16(base + AL_OFF + ar0 * PADW + akw0, &g_alw[sA0]);
        cp16(base + AL_OFF + ar1 * PADW + akw1, &g_alw[sA1]);
        size_t sB = (size_t)(set * OUTC + col0 + br_) * (IN_DIM / 2) + ch * KW + bkw0;
        cp16(base + BH_OFF + br_ * PADW + bkw0, &g_bhw[sB]);
        cp16(base + BL_OFF + br_ * PADW + bkw0, &g_blw[sB]);
        asm volatile("cp.async.commit_group;");
    };

    fill(0, 0);

    #pragma unroll 1
    for (int ch = 0; ch < NCHUNK; ch++) {
        if (ch < NCHUNK - 1) {
            fill(ch + 1, (ch + 1) & 1);
            asm volatile("cp.async.wait_group 1;");
        } else {
            asm volatile("cp.async.wait_group 0;");
        }
        __syncthreads();

        const unsigned* sAh = dsm + (ch & 1) * BUF_W + AH_OFF;
        const unsigned* sAl = dsm + (ch & 1) * BUF_W + AL_OFF;
        const unsigned* sBh = dsm + (ch & 1) * BUF_W + BH_OFF;
        const unsigned* sBl = dsm + (ch & 1) * BUF_W + BL_OFF;

        #pragma unroll
        for (int ks = 0; ks < 2; ks++) {
            unsigned ah[2][4], al[2][4], bhp[2][4], blp[2][4];
            #pragma unroll
            for (int mi = 0; mi < 2; mi++) {
                int w = (warp_m + mi * 16 + arow) * PADW + ks * 8 + akw;
                ldsm_x4(ah[mi][0], ah[mi][1], ah[mi][2], ah[mi][3], &sAh[w]);
                ldsm_x4(al[mi][0], al[mi][1], al[mi][2], al[mi][3], &sAl[w]);
            }
            #pragma unroll
            for (int p = 0; p < 2; p++) {
                int w = (warp_n + p * 16 + brow) * PADW + ks * 8 + bkw;
                ldsm_x4(bhp[p][0], bhp[p][1], bhp[p][2], bhp[p][3], &sBh[w]);
                ldsm_x4(blp[p][0], blp[p][1], blp[p][2], blp[p][3], &sBl[w]);
            }
            #pragma unroll
            for (int mi = 0; mi < 2; mi++)
                #pragma unroll
                for (int ni = 0; ni < 4; ni++) {
                    float* c = acc[mi][ni];
                    unsigned b0 = bhp[ni >> 1][(ni & 1) * 2];
                    unsigned b1 = bhp[ni >> 1][(ni & 1) * 2 + 1];
                    unsigned l0 = blp[ni >> 1][(ni & 1) * 2];
                    unsigned l1 = blp[ni >> 1][(ni & 1) * 2 + 1];
                    mma_bf16(c[0], c[1], c[2], c[3],
                             ah[mi][0], ah[mi][1], ah[mi][2], ah[mi][3], b0, b1);
                    mma_bf16(c[0], c[1], c[2], c[3],
                             ah[mi][0], ah[mi][1], ah[mi][2], ah[mi][3], l0, l1);
                    mma_bf16(c[0], c[1], c[2], c[3],
                             al[mi][0], al[mi][1], al[mi][2], al[mi][3], b0, b1);
                }
        }
        __syncthreads();
    }

    #pragma unroll
    for (int ni = 0; ni < 4; ni++) {
        int c = col0 + warp_n + ni * 8 + lr * 2;
        float b0 = bv[c], b1 = bv[c + 1];
        #pragma unroll
        for (int mi = 0; mi < 2; mi++) {
            int r_lo = row0 + warp_m + mi * 16 + lq;
            int r_hi = r_lo + 8;
            float* ac = acc[mi][ni];
            if (r_lo < N_NODES) {
                float2 o = make_float2(ac[0] + b0, ac[1] + b1);
                *(float2*)(Y + (size_t)r_lo * OUTC + c) = o;
            }
            if (r_hi < N_NODES) {
                float2 o = make_float2(ac[2] + b0, ac[3] + b1);
                *(float2*)(Y + (size_t)r_hi * OUTC + c) = o;
            }
        }
    }
}

// ---------------- CSR construction ------------------------------------------
__global__ void deg_init_kernel() {
    int i = blockIdx.x * blockDim.x + threadIdx.x;
    if (i < N_NODES) g_deg[i] = 1;
}

__global__ void deg_count_kernel(const int* __restrict__ ei) {
    int e = blockIdx.x * blockDim.x + threadIdx.x;
    if (e < N_EDGES) {
        int d = clampi(ei[N_EDGES + e], 0, N_NODES - 1);
        atomicAdd(&g_deg[d], 1);
    }
}

__global__ __launch_bounds__(SCAN_BLK) void scan_local_kernel() {
    __shared__ int s[SCAN_BLK];
    const int tid = threadIdx.x;
    const int idx = blockIdx.x * SCAN_BLK + tid;
    int v = (idx < N_NODES) ? g_deg[idx] : 0;
    int sum = v;
    #pragma unroll
    for (int off = 1; off < SCAN_BLK; off <<= 1) {
        s[tid] = sum;
        __syncthreads();
        if (tid >= off) sum += s[tid - off];
        __syncthreads();
    }
    if (idx < N_NODES) g_off[idx] = sum - v;
    if (tid == SCAN_BLK - 1) g_bsum[blockIdx.x] = sum;
}

__global__ __launch_bounds__(128) void scan_bsum_kernel() {
    __shared__ int s[128];
    const int tid = threadIdx.x;
    int v = (tid < N_SBLKS) ? g_bsum[tid] : 0;
    int sum = v;
    #pragma unroll
    for (int off = 1; off < 128; off <<= 1) {
        s[tid] = sum;
        __syncthreads();
        if (tid >= off) sum += s[tid - off];
        __syncthreads();
    }
    if (tid < N_SBLKS) g_boff[tid] = sum - v;
}

__global__ __launch_bounds__(SCAN_BLK) void scan_add_kernel() {
    const int idx = blockIdx.x * SCAN_BLK + threadIdx.x;
    if (idx < N_NODES) {
        int o = g_off[idx] + g_boff[blockIdx.x];
        g_off[idx] = o;
        g_cur[idx] = o;
    }
    if (idx == 0) g_off[N_NODES] = E_TOT;
}

__global__ void scatter_kernel(const int* __restrict__ ei) {
    int e = blockIdx.x * blockDim.x + threadIdx.x;
    if (e >= E_TOT) return;
    int s, d;
    if (e < N_EDGES) {
        s = clampi(ei[e], 0, N_NODES - 1);
        d = clampi(ei[N_EDGES + e], 0, N_NODES - 1);
    } else {
        s = d = e - N_EDGES;
    }
    int pos = atomicAdd(&g_cur[d], 1);
    g_csr[pos] = s;
}

// ---------------- GATv2 aggregation: 2 nodes/warp, 16 lanes/node, no-max -----
__global__ __launch_bounds__(256) void agg_kernel(
    const float* __restrict__ att, const float* __restrict__ bias,
    float* __restrict__ out_fc, float* __restrict__ out_pre)
{
    const int warp = (blockIdx.x * blockDim.x + threadIdx.x) >> 5;
    const int lane = threadIdx.x & 31;
    const int half = lane >> 4;
    const int sl   = lane & 15;
    const int i    = warp * 2 + half;
    const bool nv  = (i < N_NODES);

    float xr_[12], attv[12], acc[12];
    float dnm[3] = {0.f, 0.f, 0.f};
    #pragma unroll
    for (int k = 0; k < 12; k++) {
        xr_[k]  = nv ? g_xr[i * OUTC + sl + 16 * k] : 0.f;
        attv[k] = __ldg(&att[sl + 16 * k]);
        acc[k]  = 0.f;
    }

    const int beg = nv ? g_off[i] : 0;
    const int deg = nv ? (g_off[i + 1] - beg) : 0;
    const int odeg = __shfl_xor_sync(0xffffffffu, deg, 16);
    const int md = (deg > odeg) ? deg : odeg;

    for (int idx = 0; idx < md; idx++) {
        const bool valid = idx < deg;
        const int src = valid ? __ldg(&g_csr[beg + idx]) : 0;
        float xs[12];
        float p0 = 0.f, p1 = 0.f, p2 = 0.f;
        #pragma unroll
        for (int k = 0; k < 12; k++) {
            xs[k] = g_xl[src * OUTC + sl + 16 * k];
            float t = xs[k] + xr_[k];
            t = fmaxf(t, 0.2f * t);            // leaky_relu 0.2
            t *= attv[k];
            if (k < 4) p0 += t; else if (k < 8) p1 += t; else p2 += t;
        }
        #pragma unroll
        for (int off = 8; off > 0; off >>= 1) {
            p0 += __shfl_xor_sync(0xffffffffu, p0, off);
            p1 += __shfl_xor_sync(0xffffffffu, p1, off);
            p2 += __shfl_xor_sync(0xffffffffu, p2, off);
        }
        float w0 = valid ? __expf(p0) : 0.f;
        float w1 = valid ? __expf(p1) : 0.f;
        float w2 = valid ? __expf(p2) : 0.f;
        dnm[0] += w0; dnm[1] += w1; dnm[2] += w2;
        float wh[3] = {w0, w1, w2};
        #pragma unroll
        for (int k = 0; k < 12; k++)
            acc[k] = fmaf(wh[k >> 2], xs[k], acc[k]);
    }

    if (nv) {
        float inv[3];
        #pragma unroll
        for (int h = 0; h < 3; h++) inv[h] = 1.f / dnm[h];
        #pragma unroll
        for (int k = 0; k < 12; k++) {
            int c = sl + 16 * k;
            float o = acc[k] * inv[k >> 2] + bias[c];
            out_fc[i * OUTC + c] = o;
            out_pre[i * OUTC + c] = (o > 0.f) ? o : 0.01f * o;  // leaky 0.01
        }
    }
}

// ---------------- mean pool v2: grid (64 graphs, 6 col-chunks) ---------------
__global__ __launch_bounds__(256) void pool_kernel(
    const int* __restrict__ batch,
    const float* __restrict__ pre, float* __restrict__ post)
{
    const int g     = blockIdx.x;
    const int chunk = blockIdx.y;
    const int tid   = threadIdx.x;
    const int cl    = tid & 31;          // col within chunk
    const int rs    = tid >> 5;          // row slice 0..7
    const int c     = chunk * 32 + cl;

    __shared__ int sbeg, send;
    __shared__ float red[8][33];
    if (tid < 2) {
        int target = g + tid;
        int lo = 0, hi = N_NODES;
        while (lo < hi) {
            int mid = (lo + hi) >> 1;
            if (batch[mid] < target) lo = mid + 1; else hi = mid;
        }
        if (tid == 0) sbeg = lo; else send = lo;
    }
    __syncthreads();

    float sum = 0.f;
    for (int r = sbeg + rs; r < send; r += 8)
        sum += pre[(size_t)r * OUTC + c];
    red[rs][cl] = sum;
    __syncthreads();
    if (rs == 0) {
        float tot = red[0][cl] + red[1][cl] + red[2][cl] + red[3][cl]
                  + red[4][cl] + red[5][cl] + red[6][cl] + red[7][cl];
        float cnt = (float)(send - sbeg);
        post[g * OUTC + c] = tot / fmaxf(cnt, 1.f);
    }
}

// ---------------- classifier -------------------------------------------------
__global__ void cls_kernel(const float* __restrict__ post,
                           const float* __restrict__ Wc,
                           const float* __restrict__ bc,
                           float* __restrict__ logits)
{
    int t = blockIdx.x * blockDim.x + threadIdx.x;
    if (t >= NUM_GRAPHS * NUM_CLASSES) return;
    int g = t / NUM_CLASSES, c = t % NUM_CLASSES;
    float s = bc[c];
    #pragma unroll 8
    for (int k = 0; k < OUTC; k++)
        s = fmaf(post[g * OUTC + k], Wc[k * NUM_CLASSES + c], s);
    logits[g * NUM_CLASSES + c] = s;
}

// ---------------- launch -----------------------------------------------------
extern "C" void kernel_launch(void* const* d_in, const int* in_sizes, int n_in,
                              void* d_out, int out_size)
{
    const float* x     = (const float*)d_in[0];
    const int*   ei    = (const int*)d_in[1];
    const int*   batch = (const int*)d_in[2];
    const float* Wl   = (const float*)d_in[3];
    const float* bl   = (const float*)d_in[4];
    const float* Wr   = (const float*)d_in[5];
    const float* br   = (const float*)d_in[6];
    const float* att  = (const float*)d_in[7];
    const float* bias = (const float*)d_in[8];
    const float* Wc   = (const float*)d_in[9];
    const float* bc   = (const float*)d_in[10];

    float* out        = (float*)d_out;
    float* out_logits = out;
    float* out_pre    = out + NUM_GRAPHS * NUM_CLASSES;
    float* out_post   = out_pre + (size_t)N_NODES * OUTC;
    float* out_fc     = out_post + NUM_GRAPHS * OUTC;

    cudaFuncSetAttribute(mma_gemm_kernel,
                         cudaFuncAttributeMaxDynamicSharedMemorySize, SMEM_GEMM_BYTES);

    // 1-2: operand decomposition
    prep_a_kernel<<<(ROWS_PAD * 64 + 255) / 256, 256>>>(x);
    prep_b_kernel<<<(2 * OUTC * 64 + 255) / 256, 256>>>(Wl, Wr);
    // 3: CSR init (independent)
    deg_init_kernel<<<(N_NODES + 255) / 256, 256>>>();
    // 4: tensor-core GEMM (cp.async double-buffered)
    mma_gemm_kernel<<<dim3(6, N_TILES_M), 256, SMEM_GEMM_BYTES>>>(bl, br);
    // 5+: CSR build (3-phase scan)
    deg_count_kernel<<<(N_EDGES + 255) / 256, 256>>>(ei);
    scan_local_kernel<<<N_SBLKS, SCAN_BLK>>>();
    scan_bsum_kernel<<<1, 128>>>();
    scan_add_kernel<<<N_SBLKS, SCAN_BLK>>>();
    scatter_kernel<<<(E_TOT + 255) / 256, 256>>>(ei);
    // aggregation: 2 nodes per warp, exp without max-shift
    agg_kernel<<<(N_NODES / 2 * 32 + 255) / 256, 256>>>(att, bias, out_fc, out_pre);
    // mean pool (parallel v2) + classifier
    pool_kernel<<<dim3(NUM_GRAPHS, 6), 256>>>(batch, out_pre, out_post);
    cls_kernel<<<1, NUM_GRAPHS * NUM_CLASSES>>>(out_post, Wc, bc, out_logits);
}

// round 16
// speedup vs baseline: 1.5347x; 1.0206x over previous
#include <cuda_runtime.h>
#include <cuda_bf16.h>
#include <cstdint>
#include <math.h>

#define N_NODES   100000
#define N_EDGES   1600000
#define E_TOT     (N_EDGES + N_NODES)
#define IN_DIM    256
#define HID       64
#define HEADS     3
#define OUTC      (HEADS * HID)         // 192
#define NUM_CLASSES 10
#define NUM_GRAPHS  64

#define SCAN_BLK  1024
#define N_SBLKS   ((N_NODES + SCAN_BLK - 1) / SCAN_BLK)   // 98

#define M_TILE    128
#define N_TILES_M 782                   // ceil(100000/128)
#define ROWS_PAD  (N_TILES_M * M_TILE)  // 100096

// ---------------- scratch ----------------------------------------------------
__device__ float g_xl[N_NODES * OUTC];
__device__ float g_xr[N_NODES * OUTC];
__device__ int   g_deg[N_NODES + 1];
__device__ int   g_off[N_NODES + 1];
__device__ int   g_cur[N_NODES];
__device__ int   g_csr[E_TOT];
__device__ int   g_bsum[N_SBLKS];
__device__ int   g_boff[N_SBLKS];
// decomposed operands: packed bf16 pairs (k, k+1) as uint32 words
__device__ __align__(16) unsigned g_ahw[ROWS_PAD * (IN_DIM / 2)];       // hi(x)
__device__ __align__(16) unsigned g_alw[ROWS_PAD * (IN_DIM / 2)];       // lo(x)
__device__ __align__(16) unsigned g_bhw[2 * OUTC * (IN_DIM / 2)];       // hi(W^T)
__device__ __align__(16) unsigned g_blw[2 * OUTC * (IN_DIM / 2)];       // lo(W^T)

static __device__ __forceinline__ int clampi(int v, int lo, int hi) {
    return v < lo ? lo : (v > hi ? hi : v);
}

static __device__ __forceinline__ unsigned pack_bf16(unsigned short a, unsigned short b) {
    return (unsigned)a | ((unsigned)b << 16);
}

static __device__ __forceinline__ void split_bf16(float f, unsigned short& h, unsigned short& l) {
    __nv_bfloat16 hb = __float2bfloat16(f);
    __nv_bfloat16 lb = __float2bfloat16(f - __bfloat162float(hb));
    h = __bfloat16_as_ushort(hb);
    l = __bfloat16_as_ushort(lb);
}

// ---------------- prep A: x -> hi/lo bf16 packed row-major -------------------
__global__ __launch_bounds__(256) void prep_a_kernel(const float* __restrict__ x)
{
    int t = blockIdx.x * blockDim.x + threadIdx.x;
    if (t >= ROWS_PAD * 64) return;
    int k4  = t & 63;
    int row = t >> 6;
    float4 v = make_float4(0.f, 0.f, 0.f, 0.f);
    if (row < N_NODES) v = *(const float4*)(x + (size_t)row * IN_DIM + k4 * 4);
    float f[4] = {v.x, v.y, v.z, v.w};
    unsigned short h[4], l[4];
    #pragma unroll
    for (int j = 0; j < 4; j++) split_bf16(f[j], h[j], l[j]);
    int base = row * (IN_DIM / 2) + k4 * 2;
    g_ahw[base]     = pack_bf16(h[0], h[1]);
    g_ahw[base + 1] = pack_bf16(h[2], h[3]);
    g_alw[base]     = pack_bf16(l[0], l[1]);
    g_alw[base + 1] = pack_bf16(l[2], l[3]);
}

// ---------------- prep B: W[k][n] -> B^T[n][k] hi/lo bf16 packed -------------
__global__ __launch_bounds__(256) void prep_b_kernel(
    const float* __restrict__ Wl, const float* __restrict__ Wr)
{
    int t = blockIdx.x * blockDim.x + threadIdx.x;
    if (t >= 2 * OUTC * 64) return;
    int k4 = t & 63;
    int n  = (t >> 6) % OUTC;
    int s  = t / (OUTC * 64);
    const float* W = s ? Wr : Wl;
    float f[4];
    #pragma unroll
    for (int j = 0; j < 4; j++) f[j] = W[(size_t)(k4 * 4 + j) * OUTC + n];
    unsigned short h[4], l[4];
    #pragma unroll
    for (int j = 0; j < 4; j++) split_bf16(f[j], h[j], l[j]);
    int base = (s * OUTC + n) * (IN_DIM / 2) + k4 * 2;
    g_bhw[base]     = pack_bf16(h[0], h[1]);
    g_bhw[base + 1] = pack_bf16(h[2], h[3]);
    g_blw[base]     = pack_bf16(l[0], l[1]);
    g_blw[base + 1] = pack_bf16(l[2], l[3]);
}

// ---------------- HMMA GEMM: cp.async double-buffered pipeline ---------------
#define KCH    32
#define KW     (KCH / 2)                 // 16 words per row per chunk
#define PADW   20                        // padded row stride in words
#define NCHUNK (IN_DIM / KCH)            // 8

#define A_W    (128 * PADW)              // 2560 words per A array
#define B_W    (64 * PADW)               // 1280 words per B array
#define AH_OFF 0
#define AL_OFF A_W
#define BH_OFF (2 * A_W)
#define BL_OFF (2 * A_W + B_W)
#define BUF_W  (2 * A_W + 2 * B_W)       // 7680 words per buffer
#define SMEM_GEMM_BYTES (2 * BUF_W * 4)  // 61440

static __device__ __forceinline__ void mma_bf16(
    float& c0, float& c1, float& c2, float& c3,
    unsigned a0, unsigned a1, unsigned a2, unsigned a3,
    unsigned b0, unsigned b1)
{
    asm volatile(
        "mma.sync.aligned.m16n8k16.row.col.f32.bf16.bf16.f32 "
        "{%0,%1,%2,%3}, {%4,%5,%6,%7}, {%8,%9}, {%0,%1,%2,%3};"
        : "+f"(c0), "+f"(c1), "+f"(c2), "+f"(c3)
        : "r"(a0), "r"(a1), "r"(a2), "r"(a3), "r"(b0), "r"(b1));
}

static __device__ __forceinline__ void ldsm_x4(
    unsigned& r0, unsigned& r1, unsigned& r2, unsigned& r3, const unsigned* p)
{
    uint32_t a = (uint32_t)__cvta_generic_to_shared(p);
    asm volatile(
        "ldmatrix.sync.aligned.m8n8.x4.shared.b16 {%0,%1,%2,%3}, [%4];"
        : "=r"(r0), "=r"(r1), "=r"(r2), "=r"(r3) : "r"(a));
}

static __device__ __forceinline__ void cp16(unsigned* sdst, const unsigned* gsrc)
{
    uint32_t sa = (uint32_t)__cvta_generic_to_shared(sdst);
    asm volatile("cp.async.cg.shared.global [%0], [%1], 16;"
                 :: "r"(sa), "l"(gsrc));
}

__global__ __launch_bounds__(256) void mma_gemm_kernel(
    const float* __restrict__ bl, const float* __restrict__ br)
{
    extern __shared__ unsigned dsm[];

    const int tid  = threadIdx.x;
    const int wid  = tid >> 5;
    const int lane = tid & 31;
    const int cb   = blockIdx.x;
    const int tile = blockIdx.y;
    const int set  = cb / 3;
    const int nb   = cb % 3;
    const int row0 = tile * M_TILE;
    const int col0 = nb * 64;
    float* Y        = set ? g_xr : g_xl;
    const float* bv = set ? br : bl;

    const int warp_m = (wid & 3) * 32;
    const int warp_n = (wid >> 2) * 32;
    const int lq = lane >> 2;
    const int lr = lane & 3;

    const int arow = lane & 15;
    const int akw  = (lane >> 4) << 2;
    const int brow = ((lane >> 4) << 3) + (lane & 7);
    const int bkw  = (lane & 8) ? 4 : 0;

    const int ar0 = tid >> 2,        akw0 = (tid & 3) << 2;
    const int ar1 = (tid + 256) >> 2, akw1 = ((tid + 256) & 3) << 2;
    const int br_ = tid >> 2,        bkw0 = (tid & 3) << 2;

    float acc[2][4][4];
    #pragma unroll
    for (int mi = 0; mi < 2; mi++)
        #pragma unroll
        for (int ni = 0; ni < 4; ni++)
            #pragma unroll
            for (int q = 0; q < 4; q++) acc[mi][ni][q] = 0.f;

    auto fill = [&](int ch, int buf) {
        unsigned* base = dsm + buf * BUF_W;
        size_t sA0 = (size_t)(row0 + ar0) * (IN_DIM / 2) + ch * KW + akw0;
        size_t sA1 = (size_t)(row0 + ar1) * (IN_DIM / 2) + ch * KW + akw1;
        cp16(base + AH_OFF + ar0 * PADW + akw0, &g_ahw[sA0]);
        cp16(base + AH_OFF + ar1 * PADW + akw1, &g_ahw[sA1]);
        cp16(base + AL_OFF + ar0 * PADW + akw0, &g_alw[sA0]);
        cp16(base + AL_OFF + ar1 * PADW + akw1, &g_alw[sA1]);
        size_t sB = (size_t)(set * OUTC + col0 + br_) * (IN_DIM / 2) + ch * KW + bkw0;
        cp16(base + BH_OFF + br_ * PADW + bkw0, &g_bhw[sB]);
        cp16(base + BL_OFF + br_ * PADW + bkw0, &g_blw[sB]);
        asm volatile("cp.async.commit_group;");
    };

    fill(0, 0);

    #pragma unroll 1
    for (int ch = 0; ch < NCHUNK; ch++) {
        if (ch < NCHUNK - 1) {
            fill(ch + 1, (ch + 1) & 1);
            asm volatile("cp.async.wait_group 1;");
        } else {
            asm volatile("cp.async.wait_group 0;");
        }
        __syncthreads();

        const unsigned* sAh = dsm + (ch & 1) * BUF_W + AH_OFF;
        const unsigned* sAl = dsm + (ch & 1) * BUF_W + AL_OFF;
        const unsigned* sBh = dsm + (ch & 1) * BUF_W + BH_OFF;
        const unsigned* sBl = dsm + (ch & 1) * BUF_W + BL_OFF;

        #pragma unroll
        for (int ks = 0; ks < 2; ks++) {
            unsigned ah[2][4], al[2][4], bhp[2][4], blp[2][4];
            #pragma unroll
            for (int mi = 0; mi < 2; mi++) {
                int w = (warp_m + mi * 16 + arow) * PADW + ks * 8 + akw;
                ldsm_x4(ah[mi][0], ah[mi][1], ah[mi][2], ah[mi][3], &sAh[w]);
                ldsm_x4(al[mi][0], al[mi][1], al[mi][2], al[mi][3], &sAl[w]);
            }
            #pragma unroll
            for (int p = 0; p < 2; p++) {
                int w = (warp_n + p * 16 + brow) * PADW + ks * 8 + bkw;
                ldsm_x4(bhp[p][0], bhp[p][1], bhp[p][2], bhp[p][3], &sBh[w]);
                ldsm_x4(blp[p][0], blp[p][1], blp[p][2], blp[p][3], &sBl[w]);
            }
            #pragma unroll
            for (int mi = 0; mi < 2; mi++)
                #pragma unroll
                for (int ni = 0; ni < 4; ni++) {
                    float* c = acc[mi][ni];
                    unsigned b0 = bhp[ni >> 1][(ni & 1) * 2];
                    unsigned b1 = bhp[ni >> 1][(ni & 1) * 2 + 1];
                    unsigned l0 = blp[ni >> 1][(ni & 1) * 2];
                    unsigned l1 = blp[ni >> 1][(ni & 1) * 2 + 1];
                    mma_bf16(c[0], c[1], c[2], c[3],
                             ah[mi][0], ah[mi][1], ah[mi][2], ah[mi][3], b0, b1);
                    mma_bf16(c[0], c[1], c[2], c[3],
                             ah[mi][0], ah[mi][1], ah[mi][2], ah[mi][3], l0, l1);
                    mma_bf16(c[0], c[1], c[2], c[3],
                             al[mi][0], al[mi][1], al[mi][2], al[mi][3], b0, b1);
                }
        }
        __syncthreads();
    }

    #pragma unroll
    for (int ni = 0; ni < 4; ni++) {
        int c = col0 + warp_n + ni * 8 + lr * 2;
        float b0 = bv[c], b1 = bv[c + 1];
        #pragma unroll
        for (int mi = 0; mi < 2; mi++) {
            int r_lo = row0 + warp_m + mi * 16 + lq;
            int r_hi = r_lo + 8;
            float* ac = acc[mi][ni];
            if (r_lo < N_NODES) {
                float2 o = make_float2(ac[0] + b0, ac[1] + b1);
                *(float2*)(Y + (size_t)r_lo * OUTC + c) = o;
            }
            if (r_hi < N_NODES) {
                float2 o = make_float2(ac[2] + b0, ac[3] + b1);
                *(float2*)(Y + (size_t)r_hi * OUTC + c) = o;
            }
        }
    }
}

// ---------------- CSR construction ------------------------------------------
__global__ void deg_init_kernel() {
    int i = blockIdx.x * blockDim.x + threadIdx.x;
    if (i < N_NODES) g_deg[i] = 1;
}

__global__ void deg_count_kernel(const int* __restrict__ ei) {
    int e = blockIdx.x * blockDim.x + threadIdx.x;
    if (e < N_EDGES) {
        int d = clampi(ei[N_EDGES + e], 0, N_NODES - 1);
        atomicAdd(&g_deg[d], 1);
    }
}

__global__ __launch_bounds__(SCAN_BLK) void scan_local_kernel() {
    __shared__ int s[SCAN_BLK];
    const int tid = threadIdx.x;
    const int idx = blockIdx.x * SCAN_BLK + tid;
    int v = (idx < N_NODES) ? g_deg[idx] : 0;
    int sum = v;
    #pragma unroll
    for (int off = 1; off < SCAN_BLK; off <<= 1) {
        s[tid] = sum;
        __syncthreads();
        if (tid >= off) sum += s[tid - off];
        __syncthreads();
    }
    if (idx < N_NODES) g_off[idx] = sum - v;
    if (tid == SCAN_BLK - 1) g_bsum[blockIdx.x] = sum;
}

__global__ __launch_bounds__(128) void scan_bsum_kernel() {
    __shared__ int s[128];
    const int tid = threadIdx.x;
    int v = (tid < N_SBLKS) ? g_bsum[tid] : 0;
    int sum = v;
    #pragma unroll
    for (int off = 1; off < 128; off <<= 1) {
        s[tid] = sum;
        __syncthreads();
        if (tid >= off) sum += s[tid - off];
        __syncthreads();
    }
    if (tid < N_SBLKS) g_boff[tid] = sum - v;
}

__global__ __launch_bounds__(SCAN_BLK) void scan_add_kernel() {
    const int idx = blockIdx.x * SCAN_BLK + threadIdx.x;
    if (idx < N_NODES) {
        int o = g_off[idx] + g_boff[blockIdx.x];
        g_off[idx] = o;
        g_cur[idx] = o;
    }
    if (idx == 0) g_off[N_NODES] = E_TOT;
}

__global__ void scatter_kernel(const int* __restrict__ ei) {
    int e = blockIdx.x * blockDim.x + threadIdx.x;
    if (e >= E_TOT) return;
    int s, d;
    if (e < N_EDGES) {
        s = clampi(ei[e], 0, N_NODES - 1);
        d = clampi(ei[N_EDGES + e], 0, N_NODES - 1);
    } else {
        s = d = e - N_EDGES;
    }
    int pos = atomicAdd(&g_cur[d], 1);
    g_csr[pos] = s;
}

// ---------------- GATv2 agg: 2 nodes/warp, float4 gather, no-max -------------
// Lane sl owns cols c = 64*h + 4*sl + j (h=0..2, j=0..3): 3 x LDG.128 per edge.
__global__ __launch_bounds__(256) void agg_kernel(
    const float* __restrict__ att, const float* __restrict__ bias,
    float* __restrict__ out_fc, float* __restrict__ out_pre)
{
    const int warp = (blockIdx.x * blockDim.x + threadIdx.x) >> 5;
    const int lane = threadIdx.x & 31;
    const int half = lane >> 4;
    const int sl   = lane & 15;
    const int i    = warp * 2 + half;
    const bool nv  = (i < N_NODES);

    float4 xr4[3], at4[3], acc4[3];
    float dnm[3] = {0.f, 0.f, 0.f};
    #pragma unroll
    for (int h = 0; h < 3; h++) {
        int c = h * 64 + 4 * sl;
        xr4[h]  = nv ? *(const float4*)&g_xr[(size_t)i * OUTC + c]
                     : make_float4(0.f, 0.f, 0.f, 0.f);
        at4[h]  = *(const float4*)&att[c];
        acc4[h] = make_float4(0.f, 0.f, 0.f, 0.f);
    }

    const int beg = nv ? g_off[i] : 0;
    const int deg = nv ? (g_off[i + 1] - beg) : 0;
    const int odeg = __shfl_xor_sync(0xffffffffu, deg, 16);
    const int md = (deg > odeg) ? deg : odeg;

    #pragma unroll 2
    for (int idx = 0; idx < md; idx++) {
        const bool valid = idx < deg;
        const int src = valid ? __ldg(&g_csr[beg + idx]) : 0;
        float4 xs4[3];
        float p[3];
        #pragma unroll
        for (int h = 0; h < 3; h++) {
            xs4[h] = *(const float4*)&g_xl[(size_t)src * OUTC + h * 64 + 4 * sl];
            float t0 = xs4[h].x + xr4[h].x;
            float t1 = xs4[h].y + xr4[h].y;
            float t2 = xs4[h].z + xr4[h].z;
            float t3 = xs4[h].w + xr4[h].w;
            t0 = fmaxf(t0, 0.2f * t0);
            t1 = fmaxf(t1, 0.2f * t1);
            t2 = fmaxf(t2, 0.2f * t2);
            t3 = fmaxf(t3, 0.2f * t3);
            p[h] = t0 * at4[h].x + t1 * at4[h].y + t2 * at4[h].z + t3 * at4[h].w;
        }
        #pragma unroll
        for (int off = 8; off > 0; off >>= 1) {
            p[0] += __shfl_xor_sync(0xffffffffu, p[0], off);
            p[1] += __shfl_xor_sync(0xffffffffu, p[1], off);
            p[2] += __shfl_xor_sync(0xffffffffu, p[2], off);
        }
        #pragma unroll
        for (int h = 0; h < 3; h++) {
            float w = valid ? __expf(p[h]) : 0.f;
            dnm[h] += w;
            acc4[h].x = fmaf(w, xs4[h].x, acc4[h].x);
            acc4[h].y = fmaf(w, xs4[h].y, acc4[h].y);
            acc4[h].z = fmaf(w, xs4[h].z, acc4[h].z);
            acc4[h].w = fmaf(w, xs4[h].w, acc4[h].w);
        }
    }

    if (nv) {
        #pragma unroll
        for (int h = 0; h < 3; h++) {
            int c = h * 64 + 4 * sl;
            float inv = 1.f / dnm[h];
            float4 b4 = *(const float4*)&bias[c];
            float4 o, pr;
            o.x = acc4[h].x * inv + b4.x;
            o.y = acc4[h].y * inv + b4.y;
            o.z = acc4[h].z * inv + b4.z;
            o.w = acc4[h].w * inv + b4.w;
            pr.x = (o.x > 0.f) ? o.x : 0.01f * o.x;
            pr.y = (o.y > 0.f) ? o.y : 0.01f * o.y;
            pr.z = (o.z > 0.f) ? o.z : 0.01f * o.z;
            pr.w = (o.w > 0.f) ? o.w : 0.01f * o.w;
            *(float4*)&out_fc[(size_t)i * OUTC + c]  = o;
            *(float4*)&out_pre[(size_t)i * OUTC + c] = pr;
        }
    }
}

// ---------------- mean pool v2: grid (64 graphs, 6 col-chunks) ---------------
__global__ __launch_bounds__(256) void pool_kernel(
    const int* __restrict__ batch,
    const float* __restrict__ pre, float* __restrict__ post)
{
    const int g     = blockIdx.x;
    const int chunk = blockIdx.y;
    const int tid   = threadIdx.x;
    const int cl    = tid & 31;
    const int rs    = tid >> 5;
    const int c     = chunk * 32 + cl;

    __shared__ int sbeg, send;
    __shared__ float red[8][33];
    if (tid < 2) {
        int target = g + tid;
        int lo = 0, hi = N_NODES;
        while (lo < hi) {
            int mid = (lo + hi) >> 1;
            if (batch[mid] < target) lo = mid + 1; else hi = mid;
        }
        if (tid == 0) sbeg = lo; else send = lo;
    }
    __syncthreads();

    float sum = 0.f;
    for (int r = sbeg + rs; r < send; r += 8)
        sum += pre[(size_t)r * OUTC + c];
    red[rs][cl] = sum;
    __syncthreads();
    if (rs == 0) {
        float tot = red[0][cl] + red[1][cl] + red[2][cl] + red[3][cl]
                  + red[4][cl] + red[5][cl] + red[6][cl] + red[7][cl];
        float cnt = (float)(send - sbeg);
        post[g * OUTC + c] = tot / fmaxf(cnt, 1.f);
    }
}

// ---------------- classifier -------------------------------------------------
__global__ void cls_kernel(const float* __restrict__ post,
                           const float* __restrict__ Wc,
                           const float* __restrict__ bc,
                           float* __restrict__ logits)
{
    int t = blockIdx.x * blockDim.x + threadIdx.x;
    if (t >= NUM_GRAPHS * NUM_CLASSES) return;
    int g = t / NUM_CLASSES, c = t % NUM_CLASSES;
    float s = bc[c];
    #pragma unroll 8
    for (int k = 0; k < OUTC; k++)
        s = fmaf(post[g * OUTC + k], Wc[k * NUM_CLASSES + c], s);
    logits[g * NUM_CLASSES + c] = s;
}

// ---------------- launch -----------------------------------------------------
extern "C" void kernel_launch(void* const* d_in, const int* in_sizes, int n_in,
                              void* d_out, int out_size)
{
    const float* x     = (const float*)d_in[0];
    const int*   ei    = (const int*)d_in[1];
    const int*   batch = (const int*)d_in[2];
    const float* Wl   = (const float*)d_in[3];
    const float* bl   = (const float*)d_in[4];
    const float* Wr   = (const float*)d_in[5];
    const float* br   = (const float*)d_in[6];
    const float* att  = (const float*)d_in[7];
    const float* bias = (const float*)d_in[8];
    const float* Wc   = (const float*)d_in[9];
    const float* bc   = (const float*)d_in[10];

    float* out        = (float*)d_out;
    float* out_logits = out;
    float* out_pre    = out + NUM_GRAPHS * NUM_CLASSES;
    float* out_post   = out_pre + (size_t)N_NODES * OUTC;
    float* out_fc     = out_post + NUM_GRAPHS * OUTC;

    cudaFuncSetAttribute(mma_gemm_kernel,
                         cudaFuncAttributeMaxDynamicSharedMemorySize, SMEM_GEMM_BYTES);

    // 1-2: operand decomposition
    prep_a_kernel<<<(ROWS_PAD * 64 + 255) / 256, 256>>>(x);
    prep_b_kernel<<<(2 * OUTC * 64 + 255) / 256, 256>>>(Wl, Wr);
    // 3: CSR init (independent)
    deg_init_kernel<<<(N_NODES + 255) / 256, 256>>>();
    // 4: tensor-core GEMM (cp.async double-buffered)
    mma_gemm_kernel<<<dim3(6, N_TILES_M), 256, SMEM_GEMM_BYTES>>>(bl, br);
    // 5+: CSR build (3-phase scan)
    deg_count_kernel<<<(N_EDGES + 255) / 256, 256>>>(ei);
    scan_local_kernel<<<N_SBLKS, SCAN_BLK>>>();
    scan_bsum_kernel<<<1, 128>>>();
    scan_add_kernel<<<N_SBLKS, SCAN_BLK>>>();
    scatter_kernel<<<(E_TOT + 255) / 256, 256>>>(ei);
    // aggregation: 2 nodes/warp, float4 gather, no-max softmax
    agg_kernel<<<(N_NODES / 2 * 32 + 255) / 256, 256>>>(att, bias, out_fc, out_pre);
    // mean pool (parallel v2) + classifier
    pool_kernel<<<dim3(NUM_GRAPHS, 6), 256>>>(batch, out_pre, out_post);
    cls_kernel<<<1, NUM_GRAPHS * NUM_CLASSES>>>(out_post, Wc, bc, out_logits);
}